// round 16
// baseline (speedup 1.0000x reference)
#include <cuda_runtime.h>
#include <cuda_bf16.h>
#include <math.h>
#include <stdint.h>

#define NS 128
#define NV 64
#define LATD 64
#define NNODE 10000
#define EDG 160000
#define FDIM 320
#define EPSV 1e-5f
#define INV_SQ3 0.57735026918962576451f
#define INV_SQ2 0.70710678118654752440f
#define AGG_SCALE 0.25f

// ---------------------------------------------------------------------------
__device__ __forceinline__ uint32_t smem_u32(const void* p) {
    uint32_t a;
    asm("{ .reg .u64 t; cvta.to.shared.u64 t, %1; cvt.u32.u64 %0, t; }" : "=r"(a) : "l"(p));
    return a;
}
__device__ __forceinline__ float warp_sum(float v) {
#pragma unroll
    for (int o = 16; o > 0; o >>= 1) v += __shfl_xor_sync(0xffffffffu, v, o);
    return v;
}
__device__ __forceinline__ void bsplit(float x, __nv_bfloat16* ph, __nv_bfloat16* pl) {
    __nv_bfloat16 h = __float2bfloat16_rn(x);
    *ph = h;
    *pl = __float2bfloat16_rn(x - __bfloat162float(h));
}
__device__ __forceinline__ void bsplit2(float a, float b, __nv_bfloat162* H, __nv_bfloat162* L) {
    __nv_bfloat162 h, l;
    h.x = __float2bfloat16_rn(a);
    h.y = __float2bfloat16_rn(b);
    l.x = __float2bfloat16_rn(a - __bfloat162float(h.x));
    l.y = __float2bfloat16_rn(b - __bfloat162float(h.y));
    *H = h; *L = l;
}
__device__ __forceinline__ void mma_bf16(float* d, const uint32_t* a, uint32_t b0, uint32_t b1) {
    asm volatile("mma.sync.aligned.m16n8k16.row.col.f32.bf16.bf16.f32 "
        "{%0,%1,%2,%3}, {%4,%5,%6,%7}, {%8,%9}, {%0,%1,%2,%3};"
        : "+f"(d[0]), "+f"(d[1]), "+f"(d[2]), "+f"(d[3])
        : "r"(a[0]), "r"(a[1]), "r"(a[2]), "r"(a[3]), "r"(b0), "r"(b1));
}
__device__ __forceinline__ void red_v2(float* p, float a, float b) {
    asm volatile("red.global.add.v2.f32 [%0], {%1, %2};" :: "l"(p), "f"(a), "f"(b) : "memory");
}
__device__ __forceinline__ void red_v4(float* p, float a, float b, float c, float d) {
    asm volatile("red.global.add.v4.f32 [%0], {%1, %2, %3, %4};" :: "l"(p), "f"(a), "f"(b), "f"(c), "f"(d) : "memory");
}

// ---------------------------------------------------------------------------
// Global scratch (allocation-free)
// ---------------------------------------------------------------------------
__device__ float g_ns[NNODE * NS];
__device__ float g_nv[NNODE * NV * 3];
__device__ int   g_ec[EDG];

// A matrices, pre-split bf16 hi/lo
__device__ __nv_bfloat16 g_Sh[(size_t)EDG * 128], g_Sl[(size_t)EDG * 128];   // es
__device__ __nv_bfloat16 g_Dh[(size_t)EDG * 128], g_Dl[(size_t)EDG * 128];   // dotV
__device__ __nv_bfloat16 g_Vh[(size_t)3 * EDG * 64], g_Vl[(size_t)3 * EDG * 64]; // ev d-major
__device__ __nv_bfloat16 g_Lh[(size_t)EDG * 64],  g_Ll[(size_t)EDG * 64];    // latents
__device__ __nv_bfloat16 g_Uh[(size_t)EDG * 128], g_Ul[(size_t)EDG * 128];   // silu
__device__ __nv_bfloat16 g_Gh[(size_t)3 * EDG * 64], g_Gl[(size_t)3 * EDG * 64]; // gated v

// node tables (fp32, L2-resident)
__device__ float g_T1[(size_t)NNODE * 256];
__device__ float g_T3[(size_t)NNODE * 3 * 128];

// fp32 intermediates
__device__ float g_C1[(size_t)EDG * 256];
__device__ float g_gate[(size_t)EDG * 64];
__device__ float g_C3[(size_t)3 * EDG * 128];
__device__ float g_S2[(size_t)EDG * 128];
__device__ float g_V2[(size_t)3 * EDG * 64];
__device__ float g_We[(size_t)EDG * 192];

// B matrices bf16 [N x K] hi/lo
__device__ __nv_bfloat16 gB1h[256 * 128], gB1l[256 * 128];
__device__ __nv_bfloat16 gB2h[192 * 128], gB2l[192 * 128];
__device__ __nv_bfloat16 gB3h[128 * 64],  gB3l[128 * 64];
__device__ __nv_bfloat16 gBDh[128 * 128], gBDl[128 * 128];
__device__ __nv_bfloat16 gBEh[64 * 64],   gBEl[64 * 64];
__device__ __nv_bfloat16 gBFh[192 * 64],  gBFl[192 * 64];

// ---------------------------------------------------------------------------
__global__ void build_B(const float* __restrict__ Wa, const float* __restrict__ Wb,
                        int Na, int Nb, int K, int k0,
                        __nv_bfloat16* __restrict__ dh, __nv_bfloat16* __restrict__ dl)
{
    int N = Na + Nb;
    for (int idx = blockIdx.x * blockDim.x + threadIdx.x; idx < N * K; idx += gridDim.x * blockDim.x) {
        int n = idx / K, k = (idx - n * K) + k0;
        float w = (n < Na) ? Wa[(size_t)k * Na + n] : Wb[(size_t)k * Nb + (n - Na)];
        bsplit(w, &dh[idx], &dl[idx]);
    }
}

// ---------------------------------------------------------------------------
// Split-bf16 mma.sync GEMM:  C[M x N] = A @ B^T (+ table gather / fused nonlin)
// TBL: 0 none
//      1 C = acc + T[ec[r]]             (N=256 layout)
//      2 C = acc + T[(ec[e]*3+d)]       (d-major rows)
//      3 o = acc + sh0*T[r*256+col];  col<128: silu->Uh/Ul; else gate fp32
// ---------------------------------------------------------------------------
template <int N, int NT, int K, int TBL>
__global__ void __launch_bounds__(256) gemm_mma(
    const __nv_bfloat16* __restrict__ Ah, const __nv_bfloat16* __restrict__ Al,
    const __nv_bfloat16* __restrict__ Bh, const __nv_bfloat16* __restrict__ Bl,
    float* __restrict__ C, const float* __restrict__ T, const int* __restrict__ ecp,
    const float* __restrict__ esh = nullptr,
    __nv_bfloat16* __restrict__ Uh = nullptr, __nv_bfloat16* __restrict__ Ul = nullptr,
    float* __restrict__ gate = nullptr)
{
    constexpr int KP = K + 8;
    constexpr int NTILES = NT / 8;
    constexpr int NGRP = NT / 16;
    extern __shared__ __nv_bfloat16 sB[];
    __nv_bfloat16* sBh = sB;
    __nv_bfloat16* sBl = sB + NT * KP;

    int tid = threadIdx.x;
    int wm = tid >> 5, lane = tid & 31;
    int n0 = blockIdx.y * NT;
    size_t m0 = (size_t)blockIdx.x * 128;

    for (int i = tid; i < NT * (K / 8); i += 256) {
        int n = i / (K / 8), kc = (i - n * (K / 8)) * 8;
        *(uint4*)&sBh[n * KP + kc] = *(const uint4*)&Bh[(size_t)(n0 + n) * K + kc];
        *(uint4*)&sBl[n * KP + kc] = *(const uint4*)&Bl[(size_t)(n0 + n) * K + kc];
    }
    __syncthreads();

    float acc[NTILES][4];
#pragma unroll
    for (int t = 0; t < NTILES; t++)
#pragma unroll
        for (int j = 0; j < 4; j++) acc[t][j] = 0.f;

    int q = lane & 3, rr = lane >> 2;
    const __nv_bfloat16* pAh = Ah + ((size_t)m0 + wm * 16 + rr) * K + q * 2;
    const __nv_bfloat16* pAl = Al + ((size_t)m0 + wm * 16 + rr) * K + q * 2;

    int lmrow = ((lane >> 4) << 3) + (lane & 7);
    int lmk = ((lane >> 3) & 1) * 8;
    uint32_t baseh = smem_u32(sBh) + (uint32_t)(lmrow * KP + lmk) * 2;
    uint32_t basel = smem_u32(sBl) + (uint32_t)(lmrow * KP + lmk) * 2;

    uint32_t ah[4], al[4];
    ah[0] = *(const uint32_t*)(pAh);
    ah[1] = *(const uint32_t*)(pAh + 8 * K);
    ah[2] = *(const uint32_t*)(pAh + 8);
    ah[3] = *(const uint32_t*)(pAh + 8 * K + 8);
    al[0] = *(const uint32_t*)(pAl);
    al[1] = *(const uint32_t*)(pAl + 8 * K);
    al[2] = *(const uint32_t*)(pAl + 8);
    al[3] = *(const uint32_t*)(pAl + 8 * K + 8);

#pragma unroll 4
    for (int k0 = 0; k0 < K; k0 += 16) {
        int kn = (k0 + 16 < K) ? (k0 + 16) : k0;
        uint32_t nh[4], nl[4];
        nh[0] = *(const uint32_t*)(pAh + kn);
        nh[1] = *(const uint32_t*)(pAh + 8 * K + kn);
        nh[2] = *(const uint32_t*)(pAh + kn + 8);
        nh[3] = *(const uint32_t*)(pAh + 8 * K + kn + 8);
        nl[0] = *(const uint32_t*)(pAl + kn);
        nl[1] = *(const uint32_t*)(pAl + 8 * K + kn);
        nl[2] = *(const uint32_t*)(pAl + kn + 8);
        nl[3] = *(const uint32_t*)(pAl + 8 * K + kn + 8);

#pragma unroll
        for (int g = 0; g < NGRP; g++) {
            uint32_t bh0, bh1, bh2, bh3, bl0, bl1, bl2, bl3;
            uint32_t adh = baseh + (uint32_t)(g * 16 * KP + k0) * 2;
            uint32_t adl = basel + (uint32_t)(g * 16 * KP + k0) * 2;
            asm volatile("ldmatrix.sync.aligned.m8n8.x4.shared.b16 {%0,%1,%2,%3}, [%4];"
                : "=r"(bh0), "=r"(bh1), "=r"(bh2), "=r"(bh3) : "r"(adh));
            asm volatile("ldmatrix.sync.aligned.m8n8.x4.shared.b16 {%0,%1,%2,%3}, [%4];"
                : "=r"(bl0), "=r"(bl1), "=r"(bl2), "=r"(bl3) : "r"(adl));
            mma_bf16(acc[2 * g], ah, bh0, bh1);
            mma_bf16(acc[2 * g], ah, bl0, bl1);
            mma_bf16(acc[2 * g], al, bh0, bh1);
            mma_bf16(acc[2 * g + 1], ah, bh2, bh3);
            mma_bf16(acc[2 * g + 1], ah, bl2, bl3);
            mma_bf16(acc[2 * g + 1], al, bh2, bh3);
        }
#pragma unroll
        for (int j = 0; j < 4; j++) { ah[j] = nh[j]; al[j] = nl[j]; }
    }

    size_t r = m0 + wm * 16 + rr;
    const float* t0 = nullptr;
    const float* t1 = nullptr;
    float sh00 = 0.f, sh01 = 0.f;
    if (TBL == 1) {
        t0 = T + (size_t)ecp[r] * N;
        t1 = T + (size_t)ecp[r + 8] * N;
    } else if (TBL == 2) {
        int ri = (int)r;
        int d = ri / EDG, e0 = ri - d * EDG;
        t0 = T + ((size_t)ecp[e0] * 3 + d) * N;
        t1 = T + ((size_t)ecp[e0 + 8] * 3 + d) * N;
    } else if (TBL == 3) {
        t0 = T + r * 256;
        t1 = T + (r + 8) * 256;
        sh00 = esh[r * 4];
        sh01 = esh[(r + 8) * 4];
    }
#pragma unroll
    for (int t = 0; t < NTILES; t++) {
        int col = n0 + t * 8 + q * 2;
        float2 v0 = make_float2(acc[t][0], acc[t][1]);
        float2 v1 = make_float2(acc[t][2], acc[t][3]);
        if (TBL == 1 || TBL == 2) {
            float2 a0 = *(const float2*)(t0 + col);
            float2 a1 = *(const float2*)(t1 + col);
            v0.x += a0.x; v0.y += a0.y; v1.x += a1.x; v1.y += a1.y;
            *(float2*)&C[r * N + col] = v0;
            *(float2*)&C[(r + 8) * N + col] = v1;
        } else if (TBL == 3) {
            float2 a0 = *(const float2*)(t0 + col);
            float2 a1 = *(const float2*)(t1 + col);
            float o00 = v0.x + sh00 * a0.x, o01 = v0.y + sh00 * a0.y;
            float o10 = v1.x + sh01 * a1.x, o11 = v1.y + sh01 * a1.y;
            if (col < 128) {
                __nv_bfloat162 H, L;
                bsplit2(o00 / (1.f + expf(-o00)), o01 / (1.f + expf(-o01)), &H, &L);
                *(__nv_bfloat162*)&Uh[r * 128 + col] = H;
                *(__nv_bfloat162*)&Ul[r * 128 + col] = L;
                bsplit2(o10 / (1.f + expf(-o10)), o11 / (1.f + expf(-o11)), &H, &L);
                *(__nv_bfloat162*)&Uh[(r + 8) * 128 + col] = H;
                *(__nv_bfloat162*)&Ul[(r + 8) * 128 + col] = L;
            } else {
                *(float2*)&gate[r * 64 + (col - 128)] =
                    make_float2(1.f / (1.f + expf(-o00)), 1.f / (1.f + expf(-o01)));
                *(float2*)&gate[(r + 8) * 64 + (col - 128)] =
                    make_float2(1.f / (1.f + expf(-o10)), 1.f / (1.f + expf(-o11)));
            }
        } else {
            *(float2*)&C[r * N + col] = v0;
            *(float2*)&C[(r + 8) * N + col] = v1;
        }
    }
}

// ---------------------------------------------------------------------------
// node LN
// ---------------------------------------------------------------------------
__global__ void __launch_bounds__(256) node_ln_kernel(
    const float* __restrict__ nf,
    const float* __restrict__ g_s, const float* __restrict__ b_s,
    const float* __restrict__ g_v)
{
    int node = blockIdx.x * 8 + (threadIdx.x >> 5);
    int lane = threadIdx.x & 31;
    if (node >= NNODE) return;
    const float* x = nf + (size_t)node * FDIM;

    float s0[4], sum = 0.f;
#pragma unroll
    for (int i = 0; i < 4; i++) { s0[i] = x[lane + 32 * i]; sum += s0[i]; }
    sum = warp_sum(sum);
    float mu = sum * (1.f / NS), var = 0.f;
#pragma unroll
    for (int i = 0; i < 4; i++) { float d = s0[i] - mu; var += d * d; }
    var = warp_sum(var) * (1.f / NS);
    float inv = rsqrtf(var + EPSV);
#pragma unroll
    for (int i = 0; i < 4; i++) {
        int k = lane + 32 * i;
        g_ns[node * NS + k] = (s0[i] - mu) * inv * g_s[k] + b_s[k];
    }
    float vv[6], ss = 0.f;
#pragma unroll
    for (int j = 0; j < 2; j++) {
        int cc = lane + 32 * j;
#pragma unroll
        for (int d = 0; d < 3; d++) { float t = x[NS + cc * 3 + d]; vv[j * 3 + d] = t; ss += t * t; }
    }
    ss = warp_sum(ss) * (1.f / NV);
    float inv2 = rsqrtf(ss + EPSV);
#pragma unroll
    for (int j = 0; j < 2; j++) {
        int cc = lane + 32 * j;
        float g = g_v[cc];
#pragma unroll
        for (int d = 0; d < 3; d++)
            g_nv[node * (NV * 3) + cc * 3 + d] = vv[j * 3 + d] * inv2 * g;
    }
}

// ---------------------------------------------------------------------------
// node tables (fp32)
// ---------------------------------------------------------------------------
__global__ void __launch_bounds__(256) table1_kernel(
    const float* __restrict__ W_ss0, const float* __restrict__ W_sv1)
{
    __shared__ float sns[8][NS];
    int base = blockIdx.x * 8, tid = threadIdx.x;
    int w = tid >> 5, lane = tid & 31;
#pragma unroll
    for (int i = 0; i < 4; i++) sns[w][lane + 32 * i] = g_ns[(base + w) * NS + lane + 32 * i];
    __syncthreads();
    int n = tid;
    float acc[8];
#pragma unroll
    for (int e = 0; e < 8; e++) acc[e] = 0.f;
    if (n < 192) {
        for (int k = 0; k < NS; k++) {
            float wv = W_ss0[k * 192 + n];
#pragma unroll
            for (int e = 0; e < 8; e++) acc[e] += sns[e][k] * wv;
        }
    } else {
        int f = n - 192;
        for (int k = 0; k < NS; k++) {
            float wv = W_sv1[k * 64 + f];
#pragma unroll
            for (int e = 0; e < 8; e++) acc[e] += sns[e][k] * wv;
        }
    }
#pragma unroll
    for (int e = 0; e < 8; e++) g_T1[(size_t)(base + e) * 256 + n] = acc[e];
}

__global__ void __launch_bounds__(256) table3_kernel(
    const float* __restrict__ W_vs1, const float* __restrict__ W_vv1)
{
    __shared__ float snv[8][NV * 3];
    int base = blockIdx.x * 8, tid = threadIdx.x;
    int w = tid >> 5, lane = tid & 31;
#pragma unroll
    for (int i = 0; i < 6; i++) snv[w][lane + 32 * i] = g_nv[(size_t)(base + w) * (NV * 3) + lane + 32 * i];
    __syncthreads();
    for (int it = tid; it < 384; it += 256) {
        int d = it >> 7, f = it & 127;
        const float* W = (f < 64) ? &W_vs1[f] : &W_vv1[f - 64];
        float acc[8];
#pragma unroll
        for (int e = 0; e < 8; e++) acc[e] = 0.f;
        for (int c = 0; c < NV; c++) {
            float wv = W[c * 64];
#pragma unroll
            for (int e = 0; e < 8; e++) acc[e] += snv[e][c * 3 + d] * wv;
        }
#pragma unroll
        for (int e = 0; e < 8; e++) g_T3[((size_t)(base + e) * 3 + d) * 128 + f] = acc[e];
    }
}

// ---------------------------------------------------------------------------
// residual (initializes out)
// ---------------------------------------------------------------------------
__global__ void __launch_bounds__(256) residual_kernel(
    const float* __restrict__ nf, const float* __restrict__ Wr_s,
    const float* __restrict__ Wr_v, float* __restrict__ out)
{
    __shared__ float snf[8][FDIM];
    int base = blockIdx.x * 8, tid = threadIdx.x;
    int w = tid >> 5, lane = tid & 31;
    int node = base + w;
    if (node < NNODE) {
        const float* x = nf + (size_t)node * FDIM;
#pragma unroll
        for (int i = 0; i < 10; i++) snf[w][lane + 32 * i] = x[lane + 32 * i];
    }
    __syncthreads();
    int nvalid = NNODE - base; if (nvalid > 8) nvalid = 8;
    for (int it = tid; it < FDIM; it += 256) {
        float acc[8];
#pragma unroll
        for (int e = 0; e < 8; e++) acc[e] = 0.f;
        if (it < NS) {
            for (int k = 0; k < NS; k++) {
                float wv = Wr_s[k * NS + it];
#pragma unroll
                for (int e = 0; e < 8; e++) acc[e] += snf[e][k] * wv;
            }
        } else {
            int idx = it - NS, f = idx / 3, d = idx - 3 * f;
            for (int cc = 0; cc < NV; cc++) {
                float wv = Wr_v[cc * NV + f];
#pragma unroll
                for (int e = 0; e < 8; e++) acc[e] += snf[e][NS + cc * 3 + d] * wv;
            }
        }
        for (int e = 0; e < nvalid; e++) out[(size_t)(base + e) * FDIM + it] = acc[e];
    }
}

// ---------------------------------------------------------------------------
// prep: edge LN + gathers -> split-bf16 A matrices (one warp per edge)
// ---------------------------------------------------------------------------
__global__ void __launch_bounds__(256) prep_kernel(
    const float* __restrict__ latents, const float* __restrict__ edge_features,
    const float* __restrict__ edge_sh, const int* __restrict__ edge_index,
    const int* __restrict__ active_edges,
    const float* __restrict__ g_s_e, const float* __restrict__ b_s_e,
    const float* __restrict__ g_v_e)
{
    int e = blockIdx.x * 8 + (threadIdx.x >> 5);
    int lane = threadIdx.x & 31;
    int ae = active_edges[e];
    int ec = edge_index[ae];
    if (lane == 0) g_ec[e] = ec;
    const float* xf = edge_features + (size_t)e * FDIM;

    float sx = edge_sh[(size_t)e * 4 + 1];
    float sy = edge_sh[(size_t)e * 4 + 2];
    float sz = edge_sh[(size_t)e * 4 + 3];

    // scalar LN
    {
        float2 s0[2];
        float sum = 0.f;
#pragma unroll
        for (int i = 0; i < 2; i++) {
            s0[i] = *(const float2*)(xf + 2 * lane + 64 * i);
            sum += s0[i].x + s0[i].y;
        }
        sum = warp_sum(sum);
        float mu = sum * (1.f / NS), var = 0.f;
#pragma unroll
        for (int i = 0; i < 2; i++) {
            float dx = s0[i].x - mu, dy = s0[i].y - mu;
            var += dx * dx + dy * dy;
        }
        var = warp_sum(var) * (1.f / NS);
        float inv = rsqrtf(var + EPSV);
#pragma unroll
        for (int i = 0; i < 2; i++) {
            int k = 2 * lane + 64 * i;
            float a = (s0[i].x - mu) * inv * g_s_e[k] + b_s_e[k];
            float b = (s0[i].y - mu) * inv * g_s_e[k + 1] + b_s_e[k + 1];
            __nv_bfloat162 H, L;
            bsplit2(a, b, &H, &L);
            *(__nv_bfloat162*)&g_Sh[(size_t)e * 128 + k] = H;
            *(__nv_bfloat162*)&g_Sl[(size_t)e * 128 + k] = L;
        }
    }

    // vector LN
    float ev0[3], ev1[3], nv0[3], nv1[3];
    {
        const float* vf = xf + NS + 6 * lane;
        float2 p0 = *(const float2*)(vf);
        float2 p1 = *(const float2*)(vf + 2);
        float2 p2 = *(const float2*)(vf + 4);
        ev0[0] = p0.x; ev0[1] = p0.y; ev0[2] = p1.x;
        ev1[0] = p1.y; ev1[1] = p2.x; ev1[2] = p2.y;
        float ss = ev0[0]*ev0[0] + ev0[1]*ev0[1] + ev0[2]*ev0[2]
                 + ev1[0]*ev1[0] + ev1[1]*ev1[1] + ev1[2]*ev1[2];
        ss = warp_sum(ss) * (1.f / NV);
        float inv2 = rsqrtf(ss + EPSV);
        float ga = g_v_e[2 * lane], gb = g_v_e[2 * lane + 1];
#pragma unroll
        for (int d = 0; d < 3; d++) {
            ev0[d] *= inv2 * ga;
            ev1[d] *= inv2 * gb;
            __nv_bfloat162 H, L;
            bsplit2(ev0[d], ev1[d], &H, &L);
            size_t o = ((size_t)d * EDG + e) * 64 + 2 * lane;
            *(__nv_bfloat162*)&g_Vh[o] = H;
            *(__nv_bfloat162*)&g_Vl[o] = L;
        }
    }
    // node vector gather
    {
        const float* nvp = g_nv + (size_t)ec * (NV * 3) + 6 * lane;
        float2 p0 = *(const float2*)(nvp);
        float2 p1 = *(const float2*)(nvp + 2);
        float2 p2 = *(const float2*)(nvp + 4);
        nv0[0] = p0.x; nv0[1] = p0.y; nv0[2] = p1.x;
        nv1[0] = p1.y; nv1[1] = p2.x; nv1[2] = p2.y;
    }
    // D
    {
        float dn0 = (nv0[0] * sx + nv0[1] * sy + nv0[2] * sz) * INV_SQ3;
        float dn1 = (nv1[0] * sx + nv1[1] * sy + nv1[2] * sz) * INV_SQ3;
        float de0 = (ev0[0] * sx + ev0[1] * sy + ev0[2] * sz) * INV_SQ3;
        float de1 = (ev1[0] * sx + ev1[1] * sy + ev1[2] * sz) * INV_SQ3;
        __nv_bfloat162 H, L;
        bsplit2(dn0, dn1, &H, &L);
        *(__nv_bfloat162*)&g_Dh[(size_t)e * 128 + 2 * lane] = H;
        *(__nv_bfloat162*)&g_Dl[(size_t)e * 128 + 2 * lane] = L;
        bsplit2(de0, de1, &H, &L);
        *(__nv_bfloat162*)&g_Dh[(size_t)e * 128 + 64 + 2 * lane] = H;
        *(__nv_bfloat162*)&g_Dl[(size_t)e * 128 + 64 + 2 * lane] = L;
    }
    // latent gather
    {
        float2 p = *(const float2*)(latents + (size_t)ae * LATD + 2 * lane);
        __nv_bfloat162 H, L;
        bsplit2(p.x, p.y, &H, &L);
        *(__nv_bfloat162*)&g_Lh[(size_t)e * 64 + 2 * lane] = H;
        *(__nv_bfloat162*)&g_Ll[(size_t)e * 64 + 2 * lane] = L;
    }
}

// ---------------------------------------------------------------------------
// nonlin (vector part only): P, gates, C3 -> gated Vg split
// ---------------------------------------------------------------------------
__global__ void __launch_bounds__(256) nonlin_kernel(const float* __restrict__ edge_sh)
{
    int e = blockIdx.x * 8 + (threadIdx.x >> 5);
    int lane = threadIdx.x & 31;
    float sh0 = edge_sh[(size_t)e * 4 + 0];
    float sx = edge_sh[(size_t)e * 4 + 1];
    float sy = edge_sh[(size_t)e * 4 + 2];
    float sz = edge_sh[(size_t)e * 4 + 3];

    float2 gv = *(const float2*)&g_gate[(size_t)e * 64 + 2 * lane];
    float2 P = *(const float2*)&g_C1[(size_t)e * 256 + 192 + 2 * lane];
    float2 Av[3], Aw[3];
#pragma unroll
    for (int d = 0; d < 3; d++) {
        size_t r = ((size_t)d * EDG + e) * 128;
        Av[d] = *(const float2*)&g_C3[r + 2 * lane];
        Aw[d] = *(const float2*)&g_C3[r + 64 + 2 * lane];
    }
    float shv[3] = { sx, sy, sz };
    float crx[3][2];
    crx[0][0] = (Aw[1].x * sz - Aw[2].x * sy) * INV_SQ2;
    crx[1][0] = (Aw[2].x * sx - Aw[0].x * sz) * INV_SQ2;
    crx[2][0] = (Aw[0].x * sy - Aw[1].x * sx) * INV_SQ2;
    crx[0][1] = (Aw[1].y * sz - Aw[2].y * sy) * INV_SQ2;
    crx[1][1] = (Aw[2].y * sx - Aw[0].y * sz) * INV_SQ2;
    crx[2][1] = (Aw[0].y * sy - Aw[1].y * sx) * INV_SQ2;
#pragma unroll
    for (int d = 0; d < 3; d++) {
        float va = (P.x * shv[d] + sh0 * Av[d].x + crx[d][0]) * gv.x;
        float vb = (P.y * shv[d] + sh0 * Av[d].y + crx[d][1]) * gv.y;
        __nv_bfloat162 H, L;
        bsplit2(va, vb, &H, &L);
        size_t o = ((size_t)d * EDG + e) * 64 + 2 * lane;
        *(__nv_bfloat162*)&g_Gh[o] = H;
        *(__nv_bfloat162*)&g_Gl[o] = L;
    }
}

// ---------------------------------------------------------------------------
// final: env-scale + vectorized atomic scatter
// ---------------------------------------------------------------------------
__global__ void __launch_bounds__(256) final_kernel(float* __restrict__ out)
{
    int e = blockIdx.x * 8 + (threadIdx.x >> 5);
    int lane = threadIdx.x & 31;
    int ec = g_ec[e];
    float* dst = out + (size_t)ec * FDIM;
#pragma unroll
    for (int i = 0; i < 2; i++) {
        int k = 2 * lane + 64 * i;
        float2 s = *(const float2*)&g_S2[(size_t)e * 128 + k];
        float2 w = *(const float2*)&g_We[(size_t)e * 192 + k];
        red_v2(dst + k, s.x * w.x * AGG_SCALE, s.y * w.y * AGG_SCALE);
    }
    const float* we = g_We + (size_t)e * 192 + 128;
    for (int it = lane; it < 48; it += 32) {
        float v[4];
#pragma unroll
        for (int j = 0; j < 4; j++) {
            int k = 4 * it + j;
            int f = k / 3, d = k - 3 * f;
            v[j] = g_V2[((size_t)d * EDG + e) * 64 + f] * we[f] * AGG_SCALE;
        }
        red_v4(dst + NS + 4 * it, v[0], v[1], v[2], v[3]);
    }
}

// ---------------------------------------------------------------------------
extern "C" void kernel_launch(void* const* d_in, const int* in_sizes, int n_in,
                              void* d_out, int out_size)
{
    const float* latents       = (const float*)d_in[0];
    const float* node_features = (const float*)d_in[1];
    const float* edge_features = (const float*)d_in[2];
    const float* edge_sh       = (const float*)d_in[3];
    const int*   edge_index    = (const int*)  d_in[4];
    const int*   active_edges  = (const int*)  d_in[6];
    const float* g_s_n = (const float*)d_in[7];
    const float* b_s_n = (const float*)d_in[8];
    const float* g_v_n = (const float*)d_in[9];
    const float* g_s_e = (const float*)d_in[10];
    const float* b_s_e = (const float*)d_in[11];
    const float* g_v_e = (const float*)d_in[12];
    const float* W_ss0 = (const float*)d_in[13];
    const float* W_vv0 = (const float*)d_in[14];
    const float* W_sv1 = (const float*)d_in[15];
    const float* W_vs1 = (const float*)d_in[16];
    const float* W_vv1 = (const float*)d_in[17];
    const float* Wp_s  = (const float*)d_in[18];
    const float* Wp_v  = (const float*)d_in[19];
    const float* W_env = (const float*)d_in[20];
    const float* Wr_s  = (const float*)d_in[21];
    const float* Wr_v  = (const float*)d_in[22];
    float* out = (float*)d_out;

    __nv_bfloat16 *B1h, *B1l, *B2h, *B2l, *B3h, *B3l, *BDh, *BDl, *BEh, *BEl, *BFh, *BFl;
    cudaGetSymbolAddress((void**)&B1h, gB1h); cudaGetSymbolAddress((void**)&B1l, gB1l);
    cudaGetSymbolAddress((void**)&B2h, gB2h); cudaGetSymbolAddress((void**)&B2l, gB2l);
    cudaGetSymbolAddress((void**)&B3h, gB3h); cudaGetSymbolAddress((void**)&B3l, gB3l);
    cudaGetSymbolAddress((void**)&BDh, gBDh); cudaGetSymbolAddress((void**)&BDl, gBDl);
    cudaGetSymbolAddress((void**)&BEh, gBEh); cudaGetSymbolAddress((void**)&BEl, gBEl);
    cudaGetSymbolAddress((void**)&BFh, gBFh); cudaGetSymbolAddress((void**)&BFl, gBFl);
    __nv_bfloat16 *Sh, *Sl, *Dh, *Dl, *Vh, *Vl, *Lh, *Ll, *Uh, *Ul, *Gh, *Gl;
    cudaGetSymbolAddress((void**)&Sh, g_Sh); cudaGetSymbolAddress((void**)&Sl, g_Sl);
    cudaGetSymbolAddress((void**)&Dh, g_Dh); cudaGetSymbolAddress((void**)&Dl, g_Dl);
    cudaGetSymbolAddress((void**)&Vh, g_Vh); cudaGetSymbolAddress((void**)&Vl, g_Vl);
    cudaGetSymbolAddress((void**)&Lh, g_Lh); cudaGetSymbolAddress((void**)&Ll, g_Ll);
    cudaGetSymbolAddress((void**)&Uh, g_Uh); cudaGetSymbolAddress((void**)&Ul, g_Ul);
    cudaGetSymbolAddress((void**)&Gh, g_Gh); cudaGetSymbolAddress((void**)&Gl, g_Gl);
    float *C1, *gate, *C3, *S2, *V2, *We, *T1, *T3;
    cudaGetSymbolAddress((void**)&C1, g_C1); cudaGetSymbolAddress((void**)&gate, g_gate);
    cudaGetSymbolAddress((void**)&C3, g_C3); cudaGetSymbolAddress((void**)&S2, g_S2);
    cudaGetSymbolAddress((void**)&V2, g_V2); cudaGetSymbolAddress((void**)&We, g_We);
    cudaGetSymbolAddress((void**)&T1, g_T1); cudaGetSymbolAddress((void**)&T3, g_T3);
    int* ecp;
    cudaGetSymbolAddress((void**)&ecp, g_ec);

    const int SM1 = 2 * 128 * 136 * 2;  // 69632
    const int SM2 = 2 * 96 * 136 * 2;   // 52224
    const int SM3 = 2 * 128 * 72 * 2;   // 36864
    const int SM5 = 2 * 64 * 72 * 2;    // 18432
    const int SM6 = 2 * 96 * 72 * 2;    // 27648
    cudaFuncSetAttribute(gemm_mma<256, 128, 128, 1>, cudaFuncAttributeMaxDynamicSharedMemorySize, SM1);
    cudaFuncSetAttribute(gemm_mma<192, 96, 128, 3>,  cudaFuncAttributeMaxDynamicSharedMemorySize, SM2);
    cudaFuncSetAttribute(gemm_mma<128, 128, 64, 2>,  cudaFuncAttributeMaxDynamicSharedMemorySize, SM3);
    cudaFuncSetAttribute(gemm_mma<128, 128, 128, 0>, cudaFuncAttributeMaxDynamicSharedMemorySize, SM1);
    cudaFuncSetAttribute(gemm_mma<64, 64, 64, 0>,    cudaFuncAttributeMaxDynamicSharedMemorySize, SM5);
    cudaFuncSetAttribute(gemm_mma<192, 96, 64, 0>,   cudaFuncAttributeMaxDynamicSharedMemorySize, SM6);

    build_B<<<64, 256>>>(W_ss0, W_sv1, 192, 64, 128, 128, B1h, B1l);
    build_B<<<64, 256>>>(W_vv0, nullptr, 192, 0, 128, 0, B2h, B2l);
    build_B<<<64, 256>>>(W_vs1, W_vv1, 64, 64, 64, 64, B3h, B3l);
    build_B<<<64, 256>>>(Wp_s, nullptr, 128, 0, 128, 0, BDh, BDl);
    build_B<<<64, 256>>>(Wp_v, nullptr, 64, 0, 64, 0, BEh, BEl);
    build_B<<<64, 256>>>(W_env, nullptr, 192, 0, 64, 0, BFh, BFl);

    node_ln_kernel<<<(NNODE + 7) / 8, 256>>>(node_features, g_s_n, b_s_n, g_v_n);
    residual_kernel<<<(NNODE + 7) / 8, 256>>>(node_features, Wr_s, Wr_v, out);
    table1_kernel<<<NNODE / 8, 256>>>(W_ss0, W_sv1);
    table3_kernel<<<NNODE / 8, 256>>>(W_vs1, W_vv1);
    prep_kernel<<<EDG / 8, 256>>>(latents, edge_features, edge_sh, edge_index, active_edges,
                                  g_s_e, b_s_e, g_v_e);

    // C1 = [S@Wss0_e + T1 | P]
    gemm_mma<256, 128, 128, 1><<<dim3(EDG / 128, 2), 256, SM1>>>(Sh, Sl, B1h, B1l, C1, T1, ecp);
    // out0 = sh0*C1 + D@Wvv0 -> silu U / gates  (fused epilogue, no C2)
    gemm_mma<192, 96, 128, 3><<<dim3(EDG / 128, 2), 256, SM2>>>(
        Dh, Dl, B2h, B2l, nullptr, C1, nullptr, edge_sh, Uh, Ul, gate);
    // C3 = V@B3 + T3
    gemm_mma<128, 128, 64, 2><<<dim3(3 * EDG / 128, 1), 256, SM3>>>(Vh, Vl, B3h, B3l, C3, T3, ecp);

    nonlin_kernel<<<EDG / 8, 256>>>(edge_sh);

    gemm_mma<128, 128, 128, 0><<<dim3(EDG / 128, 1), 256, SM1>>>(Uh, Ul, BDh, BDl, S2, nullptr, nullptr);
    gemm_mma<64, 64, 64, 0><<<dim3(3 * EDG / 128, 1), 256, SM5>>>(Gh, Gl, BEh, BEl, V2, nullptr, nullptr);
    gemm_mma<192, 96, 64, 0><<<dim3(EDG / 128, 2), 256, SM6>>>(Lh, Ll, BFh, BFl, We, nullptr, nullptr);

    final_kernel<<<EDG / 8, 256>>>(out);
}

// round 17
// speedup vs baseline: 1.0235x; 1.0235x over previous
#include <cuda_runtime.h>
#include <cuda_bf16.h>
#include <math.h>
#include <stdint.h>

#define NS 128
#define NV 64
#define LATD 64
#define NNODE 10000
#define EDG 160000
#define FDIM 320
#define EPSV 1e-5f
#define INV_SQ3 0.57735026918962576451f
#define INV_SQ2 0.70710678118654752440f
#define AGG_SCALE 0.25f

// ---------------------------------------------------------------------------
__device__ __forceinline__ uint32_t smem_u32(const void* p) {
    uint32_t a;
    asm("{ .reg .u64 t; cvta.to.shared.u64 t, %1; cvt.u32.u64 %0, t; }" : "=r"(a) : "l"(p));
    return a;
}
__device__ __forceinline__ float warp_sum(float v) {
#pragma unroll
    for (int o = 16; o > 0; o >>= 1) v += __shfl_xor_sync(0xffffffffu, v, o);
    return v;
}
__device__ __forceinline__ void bsplit(float x, __nv_bfloat16* ph, __nv_bfloat16* pl) {
    __nv_bfloat16 h = __float2bfloat16_rn(x);
    *ph = h;
    *pl = __float2bfloat16_rn(x - __bfloat162float(h));
}
__device__ __forceinline__ void bsplit2(float a, float b, __nv_bfloat162* H, __nv_bfloat162* L) {
    __nv_bfloat162 h, l;
    h.x = __float2bfloat16_rn(a);
    h.y = __float2bfloat16_rn(b);
    l.x = __float2bfloat16_rn(a - __bfloat162float(h.x));
    l.y = __float2bfloat16_rn(b - __bfloat162float(h.y));
    *H = h; *L = l;
}
__device__ __forceinline__ void mma_bf16(float* d, const uint32_t* a, uint32_t b0, uint32_t b1) {
    asm volatile("mma.sync.aligned.m16n8k16.row.col.f32.bf16.bf16.f32 "
        "{%0,%1,%2,%3}, {%4,%5,%6,%7}, {%8,%9}, {%0,%1,%2,%3};"
        : "+f"(d[0]), "+f"(d[1]), "+f"(d[2]), "+f"(d[3])
        : "r"(a[0]), "r"(a[1]), "r"(a[2]), "r"(a[3]), "r"(b0), "r"(b1));
}
__device__ __forceinline__ void red_v2(float* p, float a, float b) {
    asm volatile("red.global.add.v2.f32 [%0], {%1, %2};" :: "l"(p), "f"(a), "f"(b) : "memory");
}
__device__ __forceinline__ void red_v4(float* p, float a, float b, float c, float d) {
    asm volatile("red.global.add.v4.f32 [%0], {%1, %2, %3, %4};" :: "l"(p), "f"(a), "f"(b), "f"(c), "f"(d) : "memory");
}

// ---------------------------------------------------------------------------
// Global scratch (allocation-free)
// ---------------------------------------------------------------------------
__device__ float g_ns[NNODE * NS];
__device__ float g_nv[NNODE * NV * 3];
__device__ int   g_ec[EDG];

// A matrices, pre-split bf16 hi/lo
__device__ __nv_bfloat16 g_Sh[(size_t)EDG * 128], g_Sl[(size_t)EDG * 128];   // es
__device__ __nv_bfloat16 g_Dh[(size_t)EDG * 128], g_Dl[(size_t)EDG * 128];   // dotV
__device__ __nv_bfloat16 g_Vh[(size_t)3 * EDG * 64], g_Vl[(size_t)3 * EDG * 64]; // ev d-major
__device__ __nv_bfloat16 g_Lh[(size_t)EDG * 64],  g_Ll[(size_t)EDG * 64];    // latents
__device__ __nv_bfloat16 g_Uh[(size_t)EDG * 128], g_Ul[(size_t)EDG * 128];   // silu
__device__ __nv_bfloat16 g_Gh[(size_t)3 * EDG * 64], g_Gl[(size_t)3 * EDG * 64]; // gated v

// node tables (fp32, L2-resident)
__device__ float g_T1[(size_t)NNODE * 256];
__device__ float g_T3[(size_t)NNODE * 3 * 128];

// fp32 intermediates
__device__ float g_C1[(size_t)EDG * 256];
__device__ float g_C2[(size_t)EDG * 192];
__device__ float g_C3[(size_t)3 * EDG * 128];
__device__ float g_S2[(size_t)EDG * 128];
__device__ float g_V2[(size_t)3 * EDG * 64];
__device__ float g_We[(size_t)EDG * 192];

// B matrices bf16 [N x K] hi/lo
__device__ __nv_bfloat16 gB1h[256 * 128], gB1l[256 * 128];
__device__ __nv_bfloat16 gB2h[192 * 128], gB2l[192 * 128];
__device__ __nv_bfloat16 gB3h[128 * 64],  gB3l[128 * 64];
__device__ __nv_bfloat16 gBDh[128 * 128], gBDl[128 * 128];
__device__ __nv_bfloat16 gBEh[64 * 64],   gBEl[64 * 64];
__device__ __nv_bfloat16 gBFh[192 * 64],  gBFl[192 * 64];

// ---------------------------------------------------------------------------
// Merged build of ALL B matrices (one launch)
// ---------------------------------------------------------------------------
__device__ __forceinline__ void build_one(
    int idx, const float* Wa, const float* Wb, int Na, int Nb, int K, int k0,
    __nv_bfloat16* dh, __nv_bfloat16* dl)
{
    int n = idx / K, k = (idx - n * K) + k0;
    float w = (n < Na) ? Wa[(size_t)k * Na + n] : Wb[(size_t)k * Nb + (n - Na)];
    bsplit(w, &dh[idx], &dl[idx]);
}

#define SEG0 32768   // B1: 256 x 128
#define SEG1 24576   // B2: 192 x 128
#define SEG2 8192    // B3: 128 x 64
#define SEG3 16384   // BD: 128 x 128
#define SEG4 4096    // BE: 64 x 64
#define SEG5 12288   // BF: 192 x 64
#define BTOT (SEG0 + SEG1 + SEG2 + SEG3 + SEG4 + SEG5)   // 98304

__global__ void __launch_bounds__(256) build_all_kernel(
    const float* __restrict__ W_ss0, const float* __restrict__ W_vv0,
    const float* __restrict__ W_sv1, const float* __restrict__ W_vs1,
    const float* __restrict__ W_vv1, const float* __restrict__ Wp_s,
    const float* __restrict__ Wp_v,  const float* __restrict__ W_env)
{
    for (int i = blockIdx.x * blockDim.x + threadIdx.x; i < BTOT; i += gridDim.x * blockDim.x) {
        int idx = i;
        if (idx < SEG0) { build_one(idx, W_ss0, W_sv1, 192, 64, 128, 128, gB1h, gB1l); continue; }
        idx -= SEG0;
        if (idx < SEG1) { build_one(idx, W_vv0, nullptr, 192, 0, 128, 0, gB2h, gB2l); continue; }
        idx -= SEG1;
        if (idx < SEG2) { build_one(idx, W_vs1, W_vv1, 64, 64, 64, 64, gB3h, gB3l); continue; }
        idx -= SEG2;
        if (idx < SEG3) { build_one(idx, Wp_s, nullptr, 128, 0, 128, 0, gBDh, gBDl); continue; }
        idx -= SEG3;
        if (idx < SEG4) { build_one(idx, Wp_v, nullptr, 64, 0, 64, 0, gBEh, gBEl); continue; }
        idx -= SEG4;
        build_one(idx, W_env, nullptr, 192, 0, 64, 0, gBFh, gBFl);
    }
}

// ---------------------------------------------------------------------------
// Split-bf16 mma.sync GEMM:  C[M x N] = A @ B^T (+ table gather)
// TBL: 0 none, 1 C += T[ec[r]], 2 (d-major rows) C += T[ec[e]*3+d]
// ---------------------------------------------------------------------------
template <int N, int NT, int K, int TBL>
__global__ void __launch_bounds__(256) gemm_mma(
    const __nv_bfloat16* __restrict__ Ah, const __nv_bfloat16* __restrict__ Al,
    const __nv_bfloat16* __restrict__ Bh, const __nv_bfloat16* __restrict__ Bl,
    float* __restrict__ C, const float* __restrict__ T, const int* __restrict__ ecp)
{
    constexpr int KP = K + 8;
    constexpr int NTILES = NT / 8;
    constexpr int NGRP = NT / 16;
    extern __shared__ __nv_bfloat16 sB[];
    __nv_bfloat16* sBh = sB;
    __nv_bfloat16* sBl = sB + NT * KP;

    int tid = threadIdx.x;
    int wm = tid >> 5, lane = tid & 31;
    int n0 = blockIdx.y * NT;
    size_t m0 = (size_t)blockIdx.x * 128;

    for (int i = tid; i < NT * (K / 8); i += 256) {
        int n = i / (K / 8), kc = (i - n * (K / 8)) * 8;
        *(uint4*)&sBh[n * KP + kc] = *(const uint4*)&Bh[(size_t)(n0 + n) * K + kc];
        *(uint4*)&sBl[n * KP + kc] = *(const uint4*)&Bl[(size_t)(n0 + n) * K + kc];
    }
    __syncthreads();

    float acc[NTILES][4];
#pragma unroll
    for (int t = 0; t < NTILES; t++)
#pragma unroll
        for (int j = 0; j < 4; j++) acc[t][j] = 0.f;

    int q = lane & 3, rr = lane >> 2;
    const __nv_bfloat16* pAh = Ah + ((size_t)m0 + wm * 16 + rr) * K + q * 2;
    const __nv_bfloat16* pAl = Al + ((size_t)m0 + wm * 16 + rr) * K + q * 2;

    int lmrow = ((lane >> 4) << 3) + (lane & 7);
    int lmk = ((lane >> 3) & 1) * 8;
    uint32_t baseh = smem_u32(sBh) + (uint32_t)(lmrow * KP + lmk) * 2;
    uint32_t basel = smem_u32(sBl) + (uint32_t)(lmrow * KP + lmk) * 2;

    uint32_t ah[4], al[4];
    ah[0] = *(const uint32_t*)(pAh);
    ah[1] = *(const uint32_t*)(pAh + 8 * K);
    ah[2] = *(const uint32_t*)(pAh + 8);
    ah[3] = *(const uint32_t*)(pAh + 8 * K + 8);
    al[0] = *(const uint32_t*)(pAl);
    al[1] = *(const uint32_t*)(pAl + 8 * K);
    al[2] = *(const uint32_t*)(pAl + 8);
    al[3] = *(const uint32_t*)(pAl + 8 * K + 8);

#pragma unroll 4
    for (int k0 = 0; k0 < K; k0 += 16) {
        int kn = (k0 + 16 < K) ? (k0 + 16) : k0;
        uint32_t nh[4], nl[4];
        nh[0] = *(const uint32_t*)(pAh + kn);
        nh[1] = *(const uint32_t*)(pAh + 8 * K + kn);
        nh[2] = *(const uint32_t*)(pAh + kn + 8);
        nh[3] = *(const uint32_t*)(pAh + 8 * K + kn + 8);
        nl[0] = *(const uint32_t*)(pAl + kn);
        nl[1] = *(const uint32_t*)(pAl + 8 * K + kn);
        nl[2] = *(const uint32_t*)(pAl + kn + 8);
        nl[3] = *(const uint32_t*)(pAl + 8 * K + kn + 8);

#pragma unroll
        for (int g = 0; g < NGRP; g++) {
            uint32_t bh0, bh1, bh2, bh3, bl0, bl1, bl2, bl3;
            uint32_t adh = baseh + (uint32_t)(g * 16 * KP + k0) * 2;
            uint32_t adl = basel + (uint32_t)(g * 16 * KP + k0) * 2;
            asm volatile("ldmatrix.sync.aligned.m8n8.x4.shared.b16 {%0,%1,%2,%3}, [%4];"
                : "=r"(bh0), "=r"(bh1), "=r"(bh2), "=r"(bh3) : "r"(adh));
            asm volatile("ldmatrix.sync.aligned.m8n8.x4.shared.b16 {%0,%1,%2,%3}, [%4];"
                : "=r"(bl0), "=r"(bl1), "=r"(bl2), "=r"(bl3) : "r"(adl));
            mma_bf16(acc[2 * g], ah, bh0, bh1);
            mma_bf16(acc[2 * g], ah, bl0, bl1);
            mma_bf16(acc[2 * g], al, bh0, bh1);
            mma_bf16(acc[2 * g + 1], ah, bh2, bh3);
            mma_bf16(acc[2 * g + 1], ah, bl2, bl3);
            mma_bf16(acc[2 * g + 1], al, bh2, bh3);
        }
#pragma unroll
        for (int j = 0; j < 4; j++) { ah[j] = nh[j]; al[j] = nl[j]; }
    }

    size_t r = m0 + wm * 16 + rr;
    const float* t0 = nullptr;
    const float* t1 = nullptr;
    if (TBL == 1) {
        t0 = T + (size_t)ecp[r] * N;
        t1 = T + (size_t)ecp[r + 8] * N;
    } else if (TBL == 2) {
        int ri = (int)r;
        int d = ri / EDG, e0 = ri - d * EDG;
        t0 = T + ((size_t)ecp[e0] * 3 + d) * N;
        t1 = T + ((size_t)ecp[e0 + 8] * 3 + d) * N;
    }
#pragma unroll
    for (int t = 0; t < NTILES; t++) {
        int col = n0 + t * 8 + q * 2;
        float2 v0 = make_float2(acc[t][0], acc[t][1]);
        float2 v1 = make_float2(acc[t][2], acc[t][3]);
        if (TBL != 0) {
            float2 a0 = *(const float2*)(t0 + col);
            float2 a1 = *(const float2*)(t1 + col);
            v0.x += a0.x; v0.y += a0.y; v1.x += a1.x; v1.y += a1.y;
        }
        *(float2*)&C[r * N + col] = v0;
        *(float2*)&C[(r + 8) * N + col] = v1;
    }
}

// ---------------------------------------------------------------------------
// merged node LN + residual: one read of node_features
// ---------------------------------------------------------------------------
__global__ void __launch_bounds__(256) node_kernel(
    const float* __restrict__ nf,
    const float* __restrict__ g_s, const float* __restrict__ b_s,
    const float* __restrict__ g_v,
    const float* __restrict__ Wr_s, const float* __restrict__ Wr_v,
    float* __restrict__ out)
{
    __shared__ float snf[8][FDIM];
    int base = blockIdx.x * 8, tid = threadIdx.x;
    int w = tid >> 5, lane = tid & 31;
    int node = base + w;
    int nvalid = NNODE - base; if (nvalid > 8) nvalid = 8;

    if (node < NNODE) {
        const float* x = nf + (size_t)node * FDIM;
#pragma unroll
        for (int i = 0; i < 10; i++) snf[w][lane + 32 * i] = x[lane + 32 * i];
    }
    __syncwarp();

    // ---- LN (per-warp, from SMEM) ----
    if (node < NNODE) {
        float s0[4], sum = 0.f;
#pragma unroll
        for (int i = 0; i < 4; i++) { s0[i] = snf[w][lane + 32 * i]; sum += s0[i]; }
        sum = warp_sum(sum);
        float mu = sum * (1.f / NS), var = 0.f;
#pragma unroll
        for (int i = 0; i < 4; i++) { float d = s0[i] - mu; var += d * d; }
        var = warp_sum(var) * (1.f / NS);
        float inv = rsqrtf(var + EPSV);
#pragma unroll
        for (int i = 0; i < 4; i++) {
            int k = lane + 32 * i;
            g_ns[node * NS + k] = (s0[i] - mu) * inv * g_s[k] + b_s[k];
        }
        float vv[6], ss = 0.f;
#pragma unroll
        for (int j = 0; j < 2; j++) {
            int cc = lane + 32 * j;
#pragma unroll
            for (int d = 0; d < 3; d++) { float t = snf[w][NS + cc * 3 + d]; vv[j * 3 + d] = t; ss += t * t; }
        }
        ss = warp_sum(ss) * (1.f / NV);
        float inv2 = rsqrtf(ss + EPSV);
#pragma unroll
        for (int j = 0; j < 2; j++) {
            int cc = lane + 32 * j;
            float g = g_v[cc];
#pragma unroll
            for (int d = 0; d < 3; d++)
                g_nv[node * (NV * 3) + cc * 3 + d] = vv[j * 3 + d] * inv2 * g;
        }
    }
    __syncthreads();

    // ---- residual GEMV ----
    for (int it = tid; it < FDIM; it += 256) {
        float acc[8];
#pragma unroll
        for (int e = 0; e < 8; e++) acc[e] = 0.f;
        if (it < NS) {
            for (int k = 0; k < NS; k++) {
                float wv = Wr_s[k * NS + it];
#pragma unroll
                for (int e = 0; e < 8; e++) acc[e] += snf[e][k] * wv;
            }
        } else {
            int idx = it - NS, f = idx / 3, d = idx - 3 * f;
            for (int cc = 0; cc < NV; cc++) {
                float wv = Wr_v[cc * NV + f];
#pragma unroll
                for (int e = 0; e < 8; e++) acc[e] += snf[e][NS + cc * 3 + d] * wv;
            }
        }
        for (int e = 0; e < nvalid; e++) out[(size_t)(base + e) * FDIM + it] = acc[e];
    }
}

// ---------------------------------------------------------------------------
// node tables (fp32)
// ---------------------------------------------------------------------------
__global__ void __launch_bounds__(256) table1_kernel(
    const float* __restrict__ W_ss0, const float* __restrict__ W_sv1)
{
    __shared__ float sns[8][NS];
    int base = blockIdx.x * 8, tid = threadIdx.x;
    int w = tid >> 5, lane = tid & 31;
#pragma unroll
    for (int i = 0; i < 4; i++) sns[w][lane + 32 * i] = g_ns[(base + w) * NS + lane + 32 * i];
    __syncthreads();
    int n = tid;
    float acc[8];
#pragma unroll
    for (int e = 0; e < 8; e++) acc[e] = 0.f;
    if (n < 192) {
        for (int k = 0; k < NS; k++) {
            float wv = W_ss0[k * 192 + n];
#pragma unroll
            for (int e = 0; e < 8; e++) acc[e] += sns[e][k] * wv;
        }
    } else {
        int f = n - 192;
        for (int k = 0; k < NS; k++) {
            float wv = W_sv1[k * 64 + f];
#pragma unroll
            for (int e = 0; e < 8; e++) acc[e] += sns[e][k] * wv;
        }
    }
#pragma unroll
    for (int e = 0; e < 8; e++) g_T1[(size_t)(base + e) * 256 + n] = acc[e];
}

__global__ void __launch_bounds__(256) table3_kernel(
    const float* __restrict__ W_vs1, const float* __restrict__ W_vv1)
{
    __shared__ float snv[8][NV * 3];
    int base = blockIdx.x * 8, tid = threadIdx.x;
    int w = tid >> 5, lane = tid & 31;
#pragma unroll
    for (int i = 0; i < 6; i++) snv[w][lane + 32 * i] = g_nv[(size_t)(base + w) * (NV * 3) + lane + 32 * i];
    __syncthreads();
    for (int it = tid; it < 384; it += 256) {
        int d = it >> 7, f = it & 127;
        const float* W = (f < 64) ? &W_vs1[f] : &W_vv1[f - 64];
        float acc[8];
#pragma unroll
        for (int e = 0; e < 8; e++) acc[e] = 0.f;
        for (int c = 0; c < NV; c++) {
            float wv = W[c * 64];
#pragma unroll
            for (int e = 0; e < 8; e++) acc[e] += snv[e][c * 3 + d] * wv;
        }
#pragma unroll
        for (int e = 0; e < 8; e++) g_T3[((size_t)(base + e) * 3 + d) * 128 + f] = acc[e];
    }
}

// ---------------------------------------------------------------------------
// prep: edge LN + gathers -> split-bf16 A matrices (one warp per edge)
// ---------------------------------------------------------------------------
__global__ void __launch_bounds__(256) prep_kernel(
    const float* __restrict__ latents, const float* __restrict__ edge_features,
    const float* __restrict__ edge_sh, const int* __restrict__ edge_index,
    const int* __restrict__ active_edges,
    const float* __restrict__ g_s_e, const float* __restrict__ b_s_e,
    const float* __restrict__ g_v_e)
{
    int e = blockIdx.x * 8 + (threadIdx.x >> 5);
    int lane = threadIdx.x & 31;
    int ae = active_edges[e];
    int ec = edge_index[ae];
    if (lane == 0) g_ec[e] = ec;
    const float* xf = edge_features + (size_t)e * FDIM;

    float sx = edge_sh[(size_t)e * 4 + 1];
    float sy = edge_sh[(size_t)e * 4 + 2];
    float sz = edge_sh[(size_t)e * 4 + 3];

    // scalar LN
    {
        float2 s0[2];
        float sum = 0.f;
#pragma unroll
        for (int i = 0; i < 2; i++) {
            s0[i] = *(const float2*)(xf + 2 * lane + 64 * i);
            sum += s0[i].x + s0[i].y;
        }
        sum = warp_sum(sum);
        float mu = sum * (1.f / NS), var = 0.f;
#pragma unroll
        for (int i = 0; i < 2; i++) {
            float dx = s0[i].x - mu, dy = s0[i].y - mu;
            var += dx * dx + dy * dy;
        }
        var = warp_sum(var) * (1.f / NS);
        float inv = rsqrtf(var + EPSV);
#pragma unroll
        for (int i = 0; i < 2; i++) {
            int k = 2 * lane + 64 * i;
            float a = (s0[i].x - mu) * inv * g_s_e[k] + b_s_e[k];
            float b = (s0[i].y - mu) * inv * g_s_e[k + 1] + b_s_e[k + 1];
            __nv_bfloat162 H, L;
            bsplit2(a, b, &H, &L);
            *(__nv_bfloat162*)&g_Sh[(size_t)e * 128 + k] = H;
            *(__nv_bfloat162*)&g_Sl[(size_t)e * 128 + k] = L;
        }
    }

    // vector LN
    float ev0[3], ev1[3], nv0[3], nv1[3];
    {
        const float* vf = xf + NS + 6 * lane;
        float2 p0 = *(const float2*)(vf);
        float2 p1 = *(const float2*)(vf + 2);
        float2 p2 = *(const float2*)(vf + 4);
        ev0[0] = p0.x; ev0[1] = p0.y; ev0[2] = p1.x;
        ev1[0] = p1.y; ev1[1] = p2.x; ev1[2] = p2.y;
        float ss = ev0[0]*ev0[0] + ev0[1]*ev0[1] + ev0[2]*ev0[2]
                 + ev1[0]*ev1[0] + ev1[1]*ev1[1] + ev1[2]*ev1[2];
        ss = warp_sum(ss) * (1.f / NV);
        float inv2 = rsqrtf(ss + EPSV);
        float ga = g_v_e[2 * lane], gb = g_v_e[2 * lane + 1];
#pragma unroll
        for (int d = 0; d < 3; d++) {
            ev0[d] *= inv2 * ga;
            ev1[d] *= inv2 * gb;
            __nv_bfloat162 H, L;
            bsplit2(ev0[d], ev1[d], &H, &L);
            size_t o = ((size_t)d * EDG + e) * 64 + 2 * lane;
            *(__nv_bfloat162*)&g_Vh[o] = H;
            *(__nv_bfloat162*)&g_Vl[o] = L;
        }
    }
    // node vector gather
    {
        const float* nvp = g_nv + (size_t)ec * (NV * 3) + 6 * lane;
        float2 p0 = *(const float2*)(nvp);
        float2 p1 = *(const float2*)(nvp + 2);
        float2 p2 = *(const float2*)(nvp + 4);
        nv0[0] = p0.x; nv0[1] = p0.y; nv0[2] = p1.x;
        nv1[0] = p1.y; nv1[1] = p2.x; nv1[2] = p2.y;
    }
    // D
    {
        float dn0 = (nv0[0] * sx + nv0[1] * sy + nv0[2] * sz) * INV_SQ3;
        float dn1 = (nv1[0] * sx + nv1[1] * sy + nv1[2] * sz) * INV_SQ3;
        float de0 = (ev0[0] * sx + ev0[1] * sy + ev0[2] * sz) * INV_SQ3;
        float de1 = (ev1[0] * sx + ev1[1] * sy + ev1[2] * sz) * INV_SQ3;
        __nv_bfloat162 H, L;
        bsplit2(dn0, dn1, &H, &L);
        *(__nv_bfloat162*)&g_Dh[(size_t)e * 128 + 2 * lane] = H;
        *(__nv_bfloat162*)&g_Dl[(size_t)e * 128 + 2 * lane] = L;
        bsplit2(de0, de1, &H, &L);
        *(__nv_bfloat162*)&g_Dh[(size_t)e * 128 + 64 + 2 * lane] = H;
        *(__nv_bfloat162*)&g_Dl[(size_t)e * 128 + 64 + 2 * lane] = L;
    }
    // latent gather
    {
        float2 p = *(const float2*)(latents + (size_t)ae * LATD + 2 * lane);
        __nv_bfloat162 H, L;
        bsplit2(p.x, p.y, &H, &L);
        *(__nv_bfloat162*)&g_Lh[(size_t)e * 64 + 2 * lane] = H;
        *(__nv_bfloat162*)&g_Ll[(size_t)e * 64 + 2 * lane] = L;
    }
}

// ---------------------------------------------------------------------------
// nonlin: combine GEMM outputs -> Silu (split) + gated Vg (split)
// ---------------------------------------------------------------------------
__global__ void __launch_bounds__(256) nonlin_kernel(const float* __restrict__ edge_sh)
{
    int e = blockIdx.x * 8 + (threadIdx.x >> 5);
    int lane = threadIdx.x & 31;
    float sh0 = edge_sh[(size_t)e * 4 + 0];
    float sx = edge_sh[(size_t)e * 4 + 1];
    float sy = edge_sh[(size_t)e * 4 + 2];
    float sz = edge_sh[(size_t)e * 4 + 3];

    float gate[2];
#pragma unroll
    for (int i = 0; i < 3; i++) {
        int f = 2 * lane + 64 * i;
        float2 c1 = *(const float2*)&g_C1[(size_t)e * 256 + f];
        float2 c2 = *(const float2*)&g_C2[(size_t)e * 192 + f];
        float oa = sh0 * c1.x + c2.x;
        float ob = sh0 * c1.y + c2.y;
        if (i < 2) {
            oa = oa / (1.f + expf(-oa));
            ob = ob / (1.f + expf(-ob));
            __nv_bfloat162 H, L;
            bsplit2(oa, ob, &H, &L);
            *(__nv_bfloat162*)&g_Uh[(size_t)e * 128 + f] = H;
            *(__nv_bfloat162*)&g_Ul[(size_t)e * 128 + f] = L;
        } else {
            gate[0] = 1.f / (1.f + expf(-oa));
            gate[1] = 1.f / (1.f + expf(-ob));
        }
    }
    float2 P = *(const float2*)&g_C1[(size_t)e * 256 + 192 + 2 * lane];
    float2 Av[3], Aw[3];
#pragma unroll
    for (int d = 0; d < 3; d++) {
        size_t r = ((size_t)d * EDG + e) * 128;
        Av[d] = *(const float2*)&g_C3[r + 2 * lane];
        Aw[d] = *(const float2*)&g_C3[r + 64 + 2 * lane];
    }
    float shv[3] = { sx, sy, sz };
    float crx[3][2];
    crx[0][0] = (Aw[1].x * sz - Aw[2].x * sy) * INV_SQ2;
    crx[1][0] = (Aw[2].x * sx - Aw[0].x * sz) * INV_SQ2;
    crx[2][0] = (Aw[0].x * sy - Aw[1].x * sx) * INV_SQ2;
    crx[0][1] = (Aw[1].y * sz - Aw[2].y * sy) * INV_SQ2;
    crx[1][1] = (Aw[2].y * sx - Aw[0].y * sz) * INV_SQ2;
    crx[2][1] = (Aw[0].y * sy - Aw[1].y * sx) * INV_SQ2;
#pragma unroll
    for (int d = 0; d < 3; d++) {
        float va = (P.x * shv[d] + sh0 * Av[d].x + crx[d][0]) * gate[0];
        float vb = (P.y * shv[d] + sh0 * Av[d].y + crx[d][1]) * gate[1];
        __nv_bfloat162 H, L;
        bsplit2(va, vb, &H, &L);
        size_t o = ((size_t)d * EDG + e) * 64 + 2 * lane;
        *(__nv_bfloat162*)&g_Gh[o] = H;
        *(__nv_bfloat162*)&g_Gl[o] = L;
    }
}

// ---------------------------------------------------------------------------
// final: env-scale + vectorized atomic scatter
// ---------------------------------------------------------------------------
__global__ void __launch_bounds__(256) final_kernel(float* __restrict__ out)
{
    int e = blockIdx.x * 8 + (threadIdx.x >> 5);
    int lane = threadIdx.x & 31;
    int ec = g_ec[e];
    float* dst = out + (size_t)ec * FDIM;
#pragma unroll
    for (int i = 0; i < 2; i++) {
        int k = 2 * lane + 64 * i;
        float2 s = *(const float2*)&g_S2[(size_t)e * 128 + k];
        float2 w = *(const float2*)&g_We[(size_t)e * 192 + k];
        red_v2(dst + k, s.x * w.x * AGG_SCALE, s.y * w.y * AGG_SCALE);
    }
    const float* we = g_We + (size_t)e * 192 + 128;
    for (int it = lane; it < 48; it += 32) {
        float v[4];
#pragma unroll
        for (int j = 0; j < 4; j++) {
            int k = 4 * it + j;
            int f = k / 3, d = k - 3 * f;
            v[j] = g_V2[((size_t)d * EDG + e) * 64 + f] * we[f] * AGG_SCALE;
        }
        red_v4(dst + NS + 4 * it, v[0], v[1], v[2], v[3]);
    }
}

// ---------------------------------------------------------------------------
extern "C" void kernel_launch(void* const* d_in, const int* in_sizes, int n_in,
                              void* d_out, int out_size)
{
    const float* latents       = (const float*)d_in[0];
    const float* node_features = (const float*)d_in[1];
    const float* edge_features = (const float*)d_in[2];
    const float* edge_sh       = (const float*)d_in[3];
    const int*   edge_index    = (const int*)  d_in[4];
    const int*   active_edges  = (const int*)  d_in[6];
    const float* g_s_n = (const float*)d_in[7];
    const float* b_s_n = (const float*)d_in[8];
    const float* g_v_n = (const float*)d_in[9];
    const float* g_s_e = (const float*)d_in[10];
    const float* b_s_e = (const float*)d_in[11];
    const float* g_v_e = (const float*)d_in[12];
    const float* W_ss0 = (const float*)d_in[13];
    const float* W_vv0 = (const float*)d_in[14];
    const float* W_sv1 = (const float*)d_in[15];
    const float* W_vs1 = (const float*)d_in[16];
    const float* W_vv1 = (const float*)d_in[17];
    const float* Wp_s  = (const float*)d_in[18];
    const float* Wp_v  = (const float*)d_in[19];
    const float* W_env = (const float*)d_in[20];
    const float* Wr_s  = (const float*)d_in[21];
    const float* Wr_v  = (const float*)d_in[22];
    float* out = (float*)d_out;

    __nv_bfloat16 *B1h, *B1l, *B2h, *B2l, *B3h, *B3l, *BDh, *BDl, *BEh, *BEl, *BFh, *BFl;
    cudaGetSymbolAddress((void**)&B1h, gB1h); cudaGetSymbolAddress((void**)&B1l, gB1l);
    cudaGetSymbolAddress((void**)&B2h, gB2h); cudaGetSymbolAddress((void**)&B2l, gB2l);
    cudaGetSymbolAddress((void**)&B3h, gB3h); cudaGetSymbolAddress((void**)&B3l, gB3l);
    cudaGetSymbolAddress((void**)&BDh, gBDh); cudaGetSymbolAddress((void**)&BDl, gBDl);
    cudaGetSymbolAddress((void**)&BEh, gBEh); cudaGetSymbolAddress((void**)&BEl, gBEl);
    cudaGetSymbolAddress((void**)&BFh, gBFh); cudaGetSymbolAddress((void**)&BFl, gBFl);
    __nv_bfloat16 *Sh, *Sl, *Dh, *Dl, *Vh, *Vl, *Lh, *Ll, *Uh, *Ul, *Gh, *Gl;
    cudaGetSymbolAddress((void**)&Sh, g_Sh); cudaGetSymbolAddress((void**)&Sl, g_Sl);
    cudaGetSymbolAddress((void**)&Dh, g_Dh); cudaGetSymbolAddress((void**)&Dl, g_Dl);
    cudaGetSymbolAddress((void**)&Vh, g_Vh); cudaGetSymbolAddress((void**)&Vl, g_Vl);
    cudaGetSymbolAddress((void**)&Lh, g_Lh); cudaGetSymbolAddress((void**)&Ll, g_Ll);
    cudaGetSymbolAddress((void**)&Uh, g_Uh); cudaGetSymbolAddress((void**)&Ul, g_Ul);
    cudaGetSymbolAddress((void**)&Gh, g_Gh); cudaGetSymbolAddress((void**)&Gl, g_Gl);
    float *C1, *C2, *C3, *S2, *V2, *We, *T1, *T3;
    cudaGetSymbolAddress((void**)&C1, g_C1); cudaGetSymbolAddress((void**)&C2, g_C2);
    cudaGetSymbolAddress((void**)&C3, g_C3); cudaGetSymbolAddress((void**)&S2, g_S2);
    cudaGetSymbolAddress((void**)&V2, g_V2); cudaGetSymbolAddress((void**)&We, g_We);
    cudaGetSymbolAddress((void**)&T1, g_T1); cudaGetSymbolAddress((void**)&T3, g_T3);
    int* ecp;
    cudaGetSymbolAddress((void**)&ecp, g_ec);

    const int SM1 = 2 * 128 * 136 * 2;  // 69632
    const int SM2 = 2 * 96 * 136 * 2;   // 52224
    const int SM3 = 2 * 128 * 72 * 2;   // 36864
    const int SM5 = 2 * 64 * 72 * 2;    // 18432
    const int SM6 = 2 * 96 * 72 * 2;    // 27648
    cudaFuncSetAttribute(gemm_mma<256, 128, 128, 1>, cudaFuncAttributeMaxDynamicSharedMemorySize, SM1);
    cudaFuncSetAttribute(gemm_mma<192, 96, 128, 0>,  cudaFuncAttributeMaxDynamicSharedMemorySize, SM2);
    cudaFuncSetAttribute(gemm_mma<128, 128, 64, 2>,  cudaFuncAttributeMaxDynamicSharedMemorySize, SM3);
    cudaFuncSetAttribute(gemm_mma<128, 128, 128, 0>, cudaFuncAttributeMaxDynamicSharedMemorySize, SM1);
    cudaFuncSetAttribute(gemm_mma<64, 64, 64, 0>,    cudaFuncAttributeMaxDynamicSharedMemorySize, SM5);
    cudaFuncSetAttribute(gemm_mma<192, 96, 64, 0>,   cudaFuncAttributeMaxDynamicSharedMemorySize, SM6);

    // all B matrices in one launch
    build_all_kernel<<<192, 256>>>(W_ss0, W_vv0, W_sv1, W_vs1, W_vv1, Wp_s, Wp_v, W_env);

    // merged node LN + residual (single read of node_features)
    node_kernel<<<(NNODE + 7) / 8, 256>>>(node_features, g_s_n, b_s_n, g_v_n, Wr_s, Wr_v, out);
    table1_kernel<<<NNODE / 8, 256>>>(W_ss0, W_sv1);
    table3_kernel<<<NNODE / 8, 256>>>(W_vs1, W_vv1);
    prep_kernel<<<EDG / 8, 256>>>(latents, edge_features, edge_sh, edge_index, active_edges,
                                  g_s_e, b_s_e, g_v_e);

    gemm_mma<256, 128, 128, 1><<<dim3(EDG / 128, 2), 256, SM1>>>(Sh, Sl, B1h, B1l, C1, T1, ecp);
    gemm_mma<192, 96, 128, 0><<<dim3(EDG / 128, 2), 256, SM2>>>(Dh, Dl, B2h, B2l, C2, nullptr, nullptr);
    gemm_mma<128, 128, 64, 2><<<dim3(3 * EDG / 128, 1), 256, SM3>>>(Vh, Vl, B3h, B3l, C3, T3, ecp);

    nonlin_kernel<<<EDG / 8, 256>>>(edge_sh);

    gemm_mma<128, 128, 128, 0><<<dim3(EDG / 128, 1), 256, SM1>>>(Uh, Ul, BDh, BDl, S2, nullptr, nullptr);
    gemm_mma<64, 64, 64, 0><<<dim3(3 * EDG / 128, 1), 256, SM5>>>(Gh, Gl, BEh, BEl, V2, nullptr, nullptr);
    gemm_mma<192, 96, 64, 0><<<dim3(EDG / 128, 2), 256, SM6>>>(Lh, Ll, BFh, BFl, We, nullptr, nullptr);

    final_kernel<<<EDG / 8, 256>>>(out);
}